// round 16
// baseline (speedup 1.0000x reference)
#include <cuda_runtime.h>
#include <cuda_fp16.h>
#include <math.h>
#include <stdint.h>

static constexpr int B = 8, C = 256, E = 64, N = 4096;

__device__ __half   g_fK[B * N * E];   // key   [b][n][islot_h(e)] fp16
__device__ __half   g_fQ[B * N * E];   // query [b][n][islot_h(e)] fp16
__device__ __half   g_hV[B * E * N];   // value [b][e][islot_h(n%16)] fp16
__device__ uint32_t g_wh[192 * 128];   // fp16x2 W(kqv) [r][pair-interleaved c]
__device__ uint32_t g_waH[256 * 32];   // fp16x2 w_att [c][pair-interleaved e]

// ---------------- helpers ----------------
__device__ __forceinline__ uint32_t smem_u32(const void* p) {
    uint32_t a;
    asm("{ .reg .u64 t; cvta.to.shared.u64 t, %1; cvt.u32.u64 %0, t; }" : "=r"(a) : "l"(p));
    return a;
}
__device__ __forceinline__ void cpasync16(uint32_t dst, const void* src) {
    asm volatile("cp.async.cg.shared.global [%0], [%1], 16;" :: "r"(dst), "l"(src));
}
#define CP_COMMIT() asm volatile("cp.async.commit_group;" ::: "memory")
#define CP_WAIT0()  asm volatile("cp.async.wait_group 0;" ::: "memory")
#define CP_WAIT2()  asm volatile("cp.async.wait_group 2;" ::: "memory")

__device__ __forceinline__ uint32_t h2pack(float lo, float hi) {
    uint32_t r;
    asm("cvt.rn.f16x2.f32 %0, %1, %2;" : "=r"(r) : "f"(hi), "f"(lo));
    return r;
}
// u32 slot of even element e within pair-interleaved stream
__device__ __forceinline__ int pslot(int e) {
    int p = (e >> 1) & 7;
    return ((e >> 4) << 3) + (((p & 3) << 1) | (p >> 2));
}
// D += A(16x16) * B(16x8), fp16 inputs, fp32 accum
__device__ __forceinline__ void mma16(float* d, const uint32_t* a, uint32_t b0, uint32_t b1) {
    asm volatile(
        "mma.sync.aligned.m16n8k16.row.col.f32.f16.f16.f32 "
        "{%0,%1,%2,%3}, {%4,%5,%6,%7}, {%8,%9}, {%0,%1,%2,%3};"
        : "+f"(d[0]), "+f"(d[1]), "+f"(d[2]), "+f"(d[3])
        : "r"(a[0]), "r"(a[1]), "r"(a[2]), "r"(a[3]), "r"(b0), "r"(b1));
}

// ---------------------------------------------------------------------------
// W pre-pass (unchanged): wk/wq/wv -> g_wh; w_att -> g_waH.
// ---------------------------------------------------------------------------
__global__ void w_pre(const float* __restrict__ wk, const float* __restrict__ wq,
                      const float* __restrict__ wv, const float* __restrict__ wa)
{
    int idx = blockIdx.x * 256 + threadIdx.x;   // 0..16383
    if (idx < 12288) {
        int r = idx >> 6, c4 = (idx & 63) << 2;
        const float* wsrc = (r < 64) ? wk + r * 256
                          : (r < 128 ? wq + (r - 64) * 256 : wv + (r - 128) * 256);
        float4 v = *(const float4*)(wsrc + c4);
        int base = r * 128 + ((c4 >> 4) << 3);
        int pb = (c4 >> 1) & 7;
        g_wh[base + (((pb & 3) << 1) | (pb >> 2))]   = h2pack(v.x, v.y);
        int pb1 = pb + 1;
        g_wh[base + (((pb1 & 3) << 1) | (pb1 >> 2))] = h2pack(v.z, v.w);
    } else {
        int i2 = idx - 12288;
        int r = i2 >> 4, c4 = (i2 & 15) << 2;
        float4 v = *(const float4*)(wa + r * 64 + c4);
        int base = r * 32 + ((c4 >> 4) << 3);
        int pb = (c4 >> 1) & 7;
        g_waH[base + (((pb & 3) << 1) | (pb >> 2))]   = h2pack(v.x, v.y);
        int pb1 = pb + 1;
        g_waH[base + (((pb1 & 3) << 1) | (pb1 >> 2))] = h2pack(v.z, v.w);
    }
}

// ---------------------------------------------------------------------------
// Projection via mma.sync fp16, 4-stage cp.async pipeline, 8 k-chunks of 32.
// W chunk smem pitch 48 halves (conflict-free A-frags); x pitch 68 f32.
// Q now emitted fp16 pair-interleaved (same rounding as before -> identical).
// grid (N/64, B), 256 thr, smem 108544 B, 2 CTAs/SM.
// ---------------------------------------------------------------------------
static constexpr int PW = 18432 / 2;   // W chunk halves (192*48)
static constexpr int PWB = 18432;      // W chunk bytes
static constexpr int PXB = 8704;       // x chunk bytes (32*68*4)

__global__ __launch_bounds__(256, 2) void proj_kernel(
    const float* __restrict__ x,
    const float* __restrict__ bk, const float* __restrict__ bq,
    const float* __restrict__ bv)
{
    extern __shared__ char ps[];
    __half* Wh = (__half*)ps;                   // 4 bufs x [192][48] halves
    float*  xs = (float*)(ps + 4 * PWB);        // 4 bufs x [32][68] f32

    const int b  = blockIdx.y;
    const int n0 = blockIdx.x << 6;
    const int tid = threadIdx.x;
    const int lane = tid & 31, w = tid >> 5;
    const int tig = lane & 3, gid = lane >> 2;
    const int wm = w & 3, wn = w >> 2;
    const float* xb = x + (size_t)b * C * N;

    auto stage = [&](int kc) {
        int bw = kc & 3;
        // W: 192 rows x 64 B (chunk kc = bytes 64*kc of each 512-B row)
        #pragma unroll
        for (int k = 0; k < 3; k++) {
            int u = tid + (k << 8);
            int row = u >> 2, q = u & 3;
            cpasync16(smem_u32(Wh + bw * PW + row * 48) + q * 16,
                      (const char*)g_wh + row * 512 + kc * 64 + q * 16);
        }
        // x: 32 c-rows x 64 n f32
        #pragma unroll
        for (int k = 0; k < 2; k++) {
            int u = tid + (k << 8);
            int crow = u >> 4, nu = u & 15;
            cpasync16(smem_u32(xs + (bw * PXB / 4) + crow * 68 + (nu << 2)),
                      xb + (size_t)(kc * 32 + crow) * N + n0 + (nu << 2));
        }
    };

    stage(0); CP_COMMIT();
    stage(1); CP_COMMIT();
    stage(2); CP_COMMIT();

    float D[3][4][4];
    #pragma unroll
    for (int mi = 0; mi < 3; mi++)
        #pragma unroll
        for (int ni = 0; ni < 4; ni++)
            #pragma unroll
            for (int i = 0; i < 4; i++) D[mi][ni][i] = 0.f;

    for (int kc = 0; kc < 8; kc++) {
        CP_WAIT2();
        __syncthreads();
        const __half* Wc = Wh + (kc & 3) * PW;
        const float*  Xc = xs + (kc & 3) * (PXB / 4);
        #pragma unroll
        for (int ks = 0; ks < 2; ks++) {
            uint32_t A[3][4];
            #pragma unroll
            for (int mi = 0; mi < 3; mi++) {
                int r1 = wm * 16 + 64 * mi + gid;
                uint2 lo = *(const uint2*)&Wc[r1 * 48 + ks * 16 + tig * 4];
                uint2 hi = *(const uint2*)&Wc[(r1 + 8) * 48 + ks * 16 + tig * 4];
                A[mi][0] = lo.x; A[mi][1] = hi.x; A[mi][2] = lo.y; A[mi][3] = hi.y;
            }
            #pragma unroll
            for (int ni = 0; ni < 4; ni++) {
                int n  = wn * 32 + ni * 8 + gid;
                int cb = ks * 16 + 2 * tig;
                uint32_t b0 = h2pack(Xc[cb * 68 + n],       Xc[(cb + 1) * 68 + n]);
                uint32_t b1 = h2pack(Xc[(cb + 8) * 68 + n], Xc[(cb + 9) * 68 + n]);
                #pragma unroll
                for (int mi = 0; mi < 3; mi++) mma16(D[mi][ni], A[mi], b0, b1);
            }
        }
        __syncthreads();
        if (kc + 3 < 8) stage(kc + 3);
        CP_COMMIT();   // unconditional (empty groups keep wait-count semantics)
    }

    const float sc = 0.0625f;
    const int nb2 = n0 + wn * 32;
    const int e0 = wm * 16 + gid;
    const bool even = (gid & 1) == 0;

    {   // K (mi=0): fp16 pairs along e via shfl_xor(4)
        float bk0 = bk[e0], bk8 = bk[e0 + 8];
        uint32_t* Kp = (uint32_t*)g_fK + (size_t)b * N * 32;
        #pragma unroll
        for (int ni = 0; ni < 4; ni++) {
            float c0 = D[0][ni][0] * sc + bk0, c1 = D[0][ni][1] * sc + bk0;
            float c2 = D[0][ni][2] * sc + bk8, c3 = D[0][ni][3] * sc + bk8;
            float p0 = __shfl_xor_sync(0xffffffffu, c0, 4);
            float p1 = __shfl_xor_sync(0xffffffffu, c1, 4);
            float p2 = __shfl_xor_sync(0xffffffffu, c2, 4);
            float p3 = __shfl_xor_sync(0xffffffffu, c3, 4);
            int n = nb2 + ni * 8 + 2 * tig;
            if (even) {
                Kp[(size_t)n * 32 + pslot(e0)]     = h2pack(c0, p0);
                Kp[(size_t)n * 32 + pslot(e0 + 8)] = h2pack(c2, p2);
            } else {
                Kp[(size_t)(n + 1) * 32 + pslot(e0 - 1)] = h2pack(p1, c1);
                Kp[(size_t)(n + 1) * 32 + pslot(e0 + 7)] = h2pack(p3, c3);
            }
        }
    }
    {   // Q (mi=1): fp16 pairs along e via shfl_xor(4) — same rounding as before
        float bq0 = bq[e0], bq8 = bq[e0 + 8];
        uint32_t* Qp = (uint32_t*)g_fQ + (size_t)b * N * 32;
        #pragma unroll
        for (int ni = 0; ni < 4; ni++) {
            float c0 = D[1][ni][0] * sc + bq0, c1 = D[1][ni][1] * sc + bq0;
            float c2 = D[1][ni][2] * sc + bq8, c3 = D[1][ni][3] * sc + bq8;
            float p0 = __shfl_xor_sync(0xffffffffu, c0, 4);
            float p1 = __shfl_xor_sync(0xffffffffu, c1, 4);
            float p2 = __shfl_xor_sync(0xffffffffu, c2, 4);
            float p3 = __shfl_xor_sync(0xffffffffu, c3, 4);
            int n = nb2 + ni * 8 + 2 * tig;
            if (even) {
                Qp[(size_t)n * 32 + pslot(e0)]     = h2pack(c0, p0);
                Qp[(size_t)n * 32 + pslot(e0 + 8)] = h2pack(c2, p2);
            } else {
                Qp[(size_t)(n + 1) * 32 + pslot(e0 - 1)] = h2pack(p1, c1);
                Qp[(size_t)(n + 1) * 32 + pslot(e0 + 7)] = h2pack(p3, c3);
            }
        }
    }
    {   // V (mi=2): fp16 pairs along n in-thread
        float bv0 = bv[e0], bv8 = bv[e0 + 8];
        uint32_t* Vp = (uint32_t*)g_hV + (size_t)b * 64 * 2048;
        #pragma unroll
        for (int ni = 0; ni < 4; ni++) {
            int n = nb2 + ni * 8 + 2 * tig;
            int slot = pslot(n);
            Vp[(size_t)e0 * 2048 + slot]       = h2pack(D[2][ni][0] * sc + bv0,
                                                        D[2][ni][1] * sc + bv0);
            Vp[(size_t)(e0 + 8) * 2048 + slot] = h2pack(D[2][ni][2] * sc + bv8,
                                                        D[2][ni][3] * sc + bv8);
        }
    }
}

// ---------------------------------------------------------------------------
// Flash attention + fused output projection + residual.
// Q now fp16 pre-interleaved (stage 8 KB, A-frags via LDS.64, pitch 80h).
// smem: Ks 2x[64][80]h | Vs 2x[64][80]h | union(Qh [128][80]h, Yt [64][132]f)
// total 74752 B, 2 CTAs/SM. grid (N/128, B), 256 thr.
// ---------------------------------------------------------------------------
static constexpr int KHALF = 5120;
static constexpr int NT = N / 64;

__global__ __launch_bounds__(256, 2) void flash_mma(
    const float* __restrict__ x, const float* __restrict__ b_att,
    const float* __restrict__ gamma, float* __restrict__ y)
{
    extern __shared__ char sraw[];
    __half* Ks = (__half*)sraw;                 // 2 bufs [64][80]h
    __half* Vs = (__half*)(sraw + 20480);       // 2 bufs [64][80]h
    __half* Qh = (__half*)(sraw + 40960);       // [128][80]h (union w/ Yt)
    float*  Yt = (float*)(sraw + 40960);        // [64][132]f epilogue

    const int tid = threadIdx.x;
    const int lane = tid & 31, w = tid >> 5;
    const int tig = lane & 3, gid = lane >> 2;
    const int b = blockIdx.y, q0 = blockIdx.x << 7;

    const __half* Kg = g_fK + (size_t)b * N * E;
    const __half* Vg = g_hV + (size_t)b * E * N;
    const __half* Qg = g_fQ + ((size_t)b * N + q0) * E;

    const int srow = tid >> 3, schunk = (tid & 7) << 3;

    // stage Q fp16 (8 KB) + K/V tile 0
    #pragma unroll
    for (int k = 0; k < 4; k++) {
        int u = tid + (k << 8);
        int row = u >> 3, q = u & 7;
        cpasync16(smem_u32(Qh + row * 80) + q * 16,
                  (const char*)Qg + row * 128 + q * 16);
    }
    #pragma unroll
    for (int p = 0; p < 2; p++) {
        int row = srow + 32 * p;
        cpasync16(smem_u32(Ks + row * 80 + schunk), Kg + (size_t)row * 64 + schunk);
        cpasync16(smem_u32(Vs + row * 80 + schunk), Vg + (size_t)row * N + schunk);
    }
    CP_COMMIT();
    CP_WAIT0();
    __syncthreads();

    // Q A-frags: single LDS.64 each (pitch 80h conflict-free)
    uint32_t qa[4][4];
    {
        const int r0 = w * 16 + gid;
        #pragma unroll
        for (int ks = 0; ks < 4; ks++) {
            uint2 lo = *(const uint2*)&Qh[r0 * 80 + ks * 16 + tig * 4];
            uint2 hi = *(const uint2*)&Qh[(r0 + 8) * 80 + ks * 16 + tig * 4];
            qa[ks][0] = lo.x; qa[ks][1] = hi.x; qa[ks][2] = lo.y; qa[ks][3] = hi.y;
        }
    }
    __syncthreads();   // Qh area free (becomes Yt later)

    float O[8][4];
    #pragma unroll
    for (int j = 0; j < 8; j++)
        #pragma unroll
        for (int i = 0; i < 4; i++) O[j][i] = 0.f;
    float m0 = -1e30f, m1 = -1e30f, l0 = 0.f, l1 = 0.f;

    for (int t = 0; t < NT; ++t) {
        const int buf = t & 1, nb = buf ^ 1;
        const bool pref = (t < NT - 1);
        const int k0n = (t + 1) << 6;

        if (pref) {
            #pragma unroll
            for (int p = 0; p < 2; p++) {
                int row = srow + 32 * p;
                cpasync16(smem_u32(Ks + nb * KHALF + row * 80 + schunk),
                          Kg + (size_t)(k0n + row) * 64 + schunk);
                cpasync16(smem_u32(Vs + nb * KHALF + row * 80 + schunk),
                          Vg + (size_t)row * N + k0n + schunk);
            }
            CP_COMMIT();
        }

        float S[8][4];
        #pragma unroll
        for (int j = 0; j < 8; j++)
            #pragma unroll
            for (int i = 0; i < 4; i++) S[j][i] = 0.f;
        {
            const __half* Kh = Ks + buf * KHALF;
            #pragma unroll
            for (int ks = 0; ks < 4; ks++) {
                int off = ks * 16 + tig * 4;
                #pragma unroll
                for (int j = 0; j < 8; j++) {
                    uint2 bb = *(const uint2*)&Kh[(gid + 8 * j) * 80 + off];
                    mma16(S[j], qa[ks], bb.x, bb.y);
                }
            }
        }

        float c0m = -1e30f, c1m = -1e30f;
        #pragma unroll
        for (int j = 0; j < 8; j++) {
            c0m = fmaxf(c0m, fmaxf(S[j][0], S[j][1]));
            c1m = fmaxf(c1m, fmaxf(S[j][2], S[j][3]));
        }
        c0m = fmaxf(c0m, __shfl_xor_sync(0xffffffffu, c0m, 1));
        c0m = fmaxf(c0m, __shfl_xor_sync(0xffffffffu, c0m, 2));
        c1m = fmaxf(c1m, __shfl_xor_sync(0xffffffffu, c1m, 1));
        c1m = fmaxf(c1m, __shfl_xor_sync(0xffffffffu, c1m, 2));
        float mn0 = fmaxf(m0, c0m), mn1 = fmaxf(m1, c1m);
        bool need = (mn0 > m0) || (mn1 > m1);
        float a0 = __expf(m0 - mn0), a1 = __expf(m1 - mn1);
        m0 = mn0; m1 = mn1;

        float s0 = 0.f, s1 = 0.f;
        #pragma unroll
        for (int j = 0; j < 8; j++) {
            S[j][0] = __expf(S[j][0] - m0); S[j][1] = __expf(S[j][1] - m0);
            S[j][2] = __expf(S[j][2] - m1); S[j][3] = __expf(S[j][3] - m1);
            s0 += S[j][0] + S[j][1];
            s1 += S[j][2] + S[j][3];
        }
        s0 += __shfl_xor_sync(0xffffffffu, s0, 1);
        s0 += __shfl_xor_sync(0xffffffffu, s0, 2);
        s1 += __shfl_xor_sync(0xffffffffu, s1, 1);
        s1 += __shfl_xor_sync(0xffffffffu, s1, 2);
        l0 = l0 * a0 + s0;
        l1 = l1 * a1 + s1;
        if (__any_sync(0xffffffffu, need)) {
            #pragma unroll
            for (int j = 0; j < 8; j++) {
                O[j][0] *= a0; O[j][1] *= a0; O[j][2] *= a1; O[j][3] *= a1;
            }
        }

        {
            const __half* Vh = Vs + buf * KHALF;
            #pragma unroll
            for (int m = 0; m < 4; m++) {
                uint32_t pa[4] = {
                    h2pack(S[2 * m][0],     S[2 * m][1]),
                    h2pack(S[2 * m][2],     S[2 * m][3]),
                    h2pack(S[2 * m + 1][0], S[2 * m + 1][1]),
                    h2pack(S[2 * m + 1][2], S[2 * m + 1][3])
                };
                int off = m * 16 + tig * 4;
                #pragma unroll
                for (int j = 0; j < 8; j++) {
                    uint2 vv = *(const uint2*)&Vh[(gid + 8 * j) * 80 + off];
                    mma16(O[j], pa, vv.x, vv.y);
                }
            }
        }

        CP_WAIT0();
        __syncthreads();
    }

    // ===== fused output projection epilogue (unchanged from R15) =====
    {
        __half* Wc = Ks;
        #pragma unroll
        for (int k = 0; k < 8; k++) {
            int u = tid + (k << 8);
            int row = u >> 3, c16 = u & 7;
            cpasync16(smem_u32(Wc + row * 80 + c16 * 8),
                      (const char*)g_waH + row * 128 + c16 * 16);
        }
        CP_COMMIT();
        CP_WAIT0();
    }
    __syncthreads();

    uint32_t pa[4][4];
    {
        float i0 = 1.f / l0, i1 = 1.f / l1;
        #pragma unroll
        for (int ks = 0; ks < 4; ks++) {
            pa[ks][0] = h2pack(O[2 * ks][0] * i0,     O[2 * ks][1] * i0);
            pa[ks][1] = h2pack(O[2 * ks][2] * i1,     O[2 * ks][3] * i1);
            pa[ks][2] = h2pack(O[2 * ks + 1][0] * i0, O[2 * ks + 1][1] * i0);
            pa[ks][3] = h2pack(O[2 * ks + 1][2] * i1, O[2 * ks + 1][3] * i1);
        }
    }

    const __half* Wc = Ks;
    const int nr = w * 16 + gid;

    #pragma unroll
    for (int cq = 0; cq < 4; cq++) {
        float D2[8][4];
        #pragma unroll
        for (int cj = 0; cj < 8; cj++)
            #pragma unroll
            for (int i = 0; i < 4; i++) D2[cj][i] = 0.f;
        #pragma unroll
        for (int ks = 0; ks < 4; ks++) {
            int off = ks * 16 + tig * 4;
            #pragma unroll
            for (int cj = 0; cj < 8; cj++) {
                uint2 bb = *(const uint2*)&Wc[(cq * 64 + cj * 8 + gid) * 80 + off];
                mma16(D2[cj], pa[ks], bb.x, bb.y);
            }
        }
        #pragma unroll
        for (int cj = 0; cj < 8; cj++) {
            int cl = cj * 8 + 2 * tig;
            Yt[cl * 132 + nr]           = D2[cj][0];
            Yt[(cl + 1) * 132 + nr]     = D2[cj][1];
            Yt[cl * 132 + nr + 8]       = D2[cj][2];
            Yt[(cl + 1) * 132 + nr + 8] = D2[cj][3];
        }
        __syncthreads();
        for (int u = tid; u < 2048; u += 256) {
            int cr = u >> 5, n4 = (u & 31) << 2;
            int c = cq * 64 + cr;
            float4 o4 = *(const float4*)&Yt[cr * 132 + n4];
            float ba = b_att[c], gm = gamma[c];
            size_t gidx = ((size_t)b * C + c) * N + q0 + n4;
            float4 x4 = *(const float4*)(x + gidx);
            float4 y4;
            y4.x = gm * (o4.x * 0.125f + ba) + x4.x;
            y4.y = gm * (o4.y * 0.125f + ba) + x4.y;
            y4.z = gm * (o4.z * 0.125f + ba) + x4.z;
            y4.w = gm * (o4.w * 0.125f + ba) + x4.w;
            *(float4*)(y + gidx) = y4;
        }
        __syncthreads();
    }
}

// ---------------------------------------------------------------------------
extern "C" void kernel_launch(void* const* d_in, const int* in_sizes, int n_in,
                              void* d_out, int out_size)
{
    const float* x  = (const float*)d_in[0];
    const float* wk = (const float*)d_in[1];
    const float* bk = (const float*)d_in[2];
    const float* wq = (const float*)d_in[3];
    const float* bq = (const float*)d_in[4];
    const float* wv = (const float*)d_in[5];
    const float* bv = (const float*)d_in[6];
    const float* wa = (const float*)d_in[7];
    const float* ba = (const float*)d_in[8];
    const float* gm = (const float*)d_in[9];
    float* y = (float*)d_out;

    cudaFuncSetAttribute(proj_kernel, cudaFuncAttributeMaxDynamicSharedMemorySize, 110592);
    cudaFuncSetAttribute(flash_mma,  cudaFuncAttributeMaxDynamicSharedMemorySize, 77824);

    w_pre<<<64, 256>>>(wk, wq, wv, wa);
    proj_kernel<<<dim3(N / 64, B), 256, 108544>>>(x, bk, bq, bv);
    flash_mma<<<dim3(N / 128, B), 256, 74752>>>(x, ba, gm, y);
}